// round 8
// baseline (speedup 1.0000x reference)
#include <cuda_runtime.h>
#include <cuda_bf16.h>

// loss_i = (label_i == label[N-1]) ? d2 : max(0, MARGIN - d2),  d2 = ||p_{N-1} - p_i||^2, D=3
// Output: scalar sum over i. Single launch, fence-free last-warp-done protocol
// (relaxed RED + acq_rel arrival counter, CUB decoupled-lookback style),
// allocation-free, graph-capturable; finisher resets globals for each replay.

#define MARGIN 500.0f
#define TPB 128
#define PTS_PER_THREAD 4

__device__ float        g_accum = 0.0f;
__device__ unsigned int g_count = 0u;

// Fence-free ordered atomics (avoids __threadfence's MEMBAR.GPU + CCTL.IVALL L1 flush)
__device__ __forceinline__ void red_add_f32_relaxed(float* p, float v) {
    asm volatile("red.relaxed.gpu.add.f32 [%0], %1;" :: "l"(p), "f"(v) : "memory");
}
__device__ __forceinline__ unsigned atom_add_u32_acqrel(unsigned* p, unsigned v) {
    unsigned old;
    asm volatile("atom.acq_rel.gpu.add.u32 %0, [%1], %2;"
                 : "=r"(old) : "l"(p), "r"(v) : "memory");
    return old;
}
__device__ __forceinline__ float atom_exch_f32_acquire(float* p, float v) {
    unsigned old;
    asm volatile("atom.acquire.gpu.exch.b32 %0, [%1], %2;"
                 : "=r"(old) : "l"(p), "r"(__float_as_uint(v)) : "memory");
    return __uint_as_float(old);
}

__global__ __launch_bounds__(TPB)
void contrastive_last_anchor_kernel(const int* __restrict__ labels,
                                    const float* __restrict__ coords,
                                    float* __restrict__ out,
                                    int n, unsigned int total_warps)
{
    const int t    = blockIdx.x * TPB + threadIdx.x;
    const int base = t * PTS_PER_THREAD;

    // ---- Issue all wide loads up front (independent -> batched MLP) ----
    int4   lab = make_int4(0, 0, 0, 0);
    float4 c0 = make_float4(0.f, 0.f, 0.f, 0.f);
    float4 c1 = c0, c2 = c0;
    const bool full = (base + PTS_PER_THREAD <= n);
    if (full) {
        lab = *reinterpret_cast<const int4*>(labels + base);                    // 16B aligned
        const float4* cp = reinterpret_cast<const float4*>(coords + 3 * base);  // 48B/thread -> 16B aligned
        c0 = cp[0]; c1 = cp[1]; c2 = cp[2];
    }

    // Anchor (same 2 cache lines chip-wide -> broadcast, overlaps above loads)
    const int   al = __ldg(labels + (n - 1));
    const float ax = __ldg(coords + 3 * (n - 1) + 0);
    const float ay = __ldg(coords + 3 * (n - 1) + 1);
    const float az = __ldg(coords + 3 * (n - 1) + 2);

    float v = 0.0f;
    if (full) {
        // p0=(c0.x,c0.y,c0.z) p1=(c0.w,c1.x,c1.y) p2=(c1.z,c1.w,c2.x) p3=(c2.y,c2.z,c2.w)
        {
            const float dx = ax - c0.x, dy = ay - c0.y, dz = az - c0.z;
            const float d2 = fmaf(dx, dx, fmaf(dy, dy, dz * dz));
            v += (lab.x == al) ? d2 : fmaxf(0.0f, MARGIN - d2);
        }
        {
            const float dx = ax - c0.w, dy = ay - c1.x, dz = az - c1.y;
            const float d2 = fmaf(dx, dx, fmaf(dy, dy, dz * dz));
            v += (lab.y == al) ? d2 : fmaxf(0.0f, MARGIN - d2);
        }
        {
            const float dx = ax - c1.z, dy = ay - c1.w, dz = az - c2.x;
            const float d2 = fmaf(dx, dx, fmaf(dy, dy, dz * dz));
            v += (lab.z == al) ? d2 : fmaxf(0.0f, MARGIN - d2);
        }
        {
            const float dx = ax - c2.y, dy = ay - c2.z, dz = az - c2.w;
            const float d2 = fmaf(dx, dx, fmaf(dy, dy, dz * dz));
            v += (lab.w == al) ? d2 : fmaxf(0.0f, MARGIN - d2);
        }
    } else {
        for (int i = base; i < n && i < base + PTS_PER_THREAD; i++) {
            const float dx = ax - coords[3 * i + 0];
            const float dy = ay - coords[3 * i + 1];
            const float dz = az - coords[3 * i + 2];
            const float d2 = fmaf(dx, dx, fmaf(dy, dy, dz * dz));
            v += (labels[i] == al) ? d2 : fmaxf(0.0f, MARGIN - d2);
        }
    }

    // ---- Warp reduce (5 shfl), then fence-free global protocol ----
    #pragma unroll
    for (int o = 16; o > 0; o >>= 1)
        v += __shfl_down_sync(0xFFFFFFFFu, v, o);

    if ((threadIdx.x & 31) == 0) {
        // RED (no return) into accumulator; release on the counter orders it.
        red_add_f32_relaxed(&g_accum, v);
        const unsigned old = atom_add_u32_acqrel(&g_count, 1u);
        if (old == total_warps - 1u) {
            // acquire on the final count makes all REDs visible; exch reads
            // the total AND resets the accumulator for the next replay.
            const float total = atom_exch_f32_acquire(&g_accum, 0.0f);
            out[0] = total;
            atomicExch(&g_count, 0u);   // reset arrival counter for next replay
        }
    }
}

extern "C" void kernel_launch(void* const* d_in, const int* in_sizes, int n_in,
                              void* d_out, int out_size)
{
    const int*   labels = (const int*)d_in[0];
    const float* coords = (const float*)d_in[1];
    float*       out    = (float*)d_out;
    const int n = in_sizes[0];

    const int pts_per_cta = TPB * PTS_PER_THREAD;                 // 512
    const int blocks = (n + pts_per_cta - 1) / pts_per_cta;       // 64 for n=32768
    const unsigned total_warps = (unsigned)blocks * (TPB / 32);   // 256

    contrastive_last_anchor_kernel<<<blocks, TPB>>>(labels, coords, out, n, total_warps);
}

// round 9
// speedup vs baseline: 1.1208x; 1.1208x over previous
#include <cuda_runtime.h>
#include <cuda_bf16.h>

// loss_i = (label_i == label[N-1]) ? d2 : max(0, MARGIN - d2),  d2 = ||p_{N-1}-p_i||^2, D=3
// Output: scalar sum. Two graph nodes: (1) zero out[0], (2) every warp
// warp-reduces and fire-and-forget REDs into out[0]. No completion protocol,
// no device globals, no finisher tail. Stream order inside the graph orders
// the zero before all adds on every replay; kernel completion makes the REDs
// visible to the harness. Allocation-free, graph-capturable, deterministic
// (up to fp atomic ordering, ~1e-7 rel err).

#define MARGIN 500.0f
#define TPB 128
#define PTS_PER_THREAD 4

__global__ void zero_out_kernel(float* __restrict__ out) {
    out[0] = 0.0f;
}

__device__ __forceinline__ void red_add_f32_relaxed(float* p, float v) {
    asm volatile("red.relaxed.gpu.add.f32 [%0], %1;" :: "l"(p), "f"(v) : "memory");
}

__global__ __launch_bounds__(TPB)
void contrastive_last_anchor_kernel(const int* __restrict__ labels,
                                    const float* __restrict__ coords,
                                    float* __restrict__ out,
                                    int n)
{
    const int t    = blockIdx.x * TPB + threadIdx.x;
    const int base = t * PTS_PER_THREAD;

    // ---- All wide loads issued up front (independent -> batched MLP) ----
    int4   lab = make_int4(0, 0, 0, 0);
    float4 c0 = make_float4(0.f, 0.f, 0.f, 0.f);
    float4 c1 = c0, c2 = c0;
    const bool full = (base + PTS_PER_THREAD <= n);
    if (full) {
        lab = *reinterpret_cast<const int4*>(labels + base);                    // 16B aligned
        const float4* cp = reinterpret_cast<const float4*>(coords + 3 * base);  // 48B/thread -> 16B aligned
        c0 = cp[0]; c1 = cp[1]; c2 = cp[2];
    }

    // Anchor: same 2 cache lines chip-wide -> broadcast; overlaps loads above.
    const int   al = __ldg(labels + (n - 1));
    const float ax = __ldg(coords + 3 * (n - 1) + 0);
    const float ay = __ldg(coords + 3 * (n - 1) + 1);
    const float az = __ldg(coords + 3 * (n - 1) + 2);

    float v = 0.0f;
    if (full) {
        // p0=(c0.x,c0.y,c0.z) p1=(c0.w,c1.x,c1.y) p2=(c1.z,c1.w,c2.x) p3=(c2.y,c2.z,c2.w)
        {
            const float dx = ax - c0.x, dy = ay - c0.y, dz = az - c0.z;
            const float d2 = fmaf(dx, dx, fmaf(dy, dy, dz * dz));
            v += (lab.x == al) ? d2 : fmaxf(0.0f, MARGIN - d2);
        }
        {
            const float dx = ax - c0.w, dy = ay - c1.x, dz = az - c1.y;
            const float d2 = fmaf(dx, dx, fmaf(dy, dy, dz * dz));
            v += (lab.y == al) ? d2 : fmaxf(0.0f, MARGIN - d2);
        }
        {
            const float dx = ax - c1.z, dy = ay - c1.w, dz = az - c2.x;
            const float d2 = fmaf(dx, dx, fmaf(dy, dy, dz * dz));
            v += (lab.z == al) ? d2 : fmaxf(0.0f, MARGIN - d2);
        }
        {
            const float dx = ax - c2.y, dy = ay - c2.z, dz = az - c2.w;
            const float d2 = fmaf(dx, dx, fmaf(dy, dy, dz * dz));
            v += (lab.w == al) ? d2 : fmaxf(0.0f, MARGIN - d2);
        }
    } else {
        for (int i = base; i < n && i < base + PTS_PER_THREAD; i++) {
            const float dx = ax - coords[3 * i + 0];
            const float dy = ay - coords[3 * i + 1];
            const float dz = az - coords[3 * i + 2];
            const float d2 = fmaf(dx, dx, fmaf(dy, dy, dz * dz));
            v += (labels[i] == al) ? d2 : fmaxf(0.0f, MARGIN - d2);
        }
    }

    // ---- Warp reduce (5 shfl), then one fire-and-forget RED per warp ----
    #pragma unroll
    for (int o = 16; o > 0; o >>= 1)
        v += __shfl_down_sync(0xFFFFFFFFu, v, o);

    if ((threadIdx.x & 31) == 0)
        red_add_f32_relaxed(out, v);   // no return, no dependent chain
}

extern "C" void kernel_launch(void* const* d_in, const int* in_sizes, int n_in,
                              void* d_out, int out_size)
{
    const int*   labels = (const int*)d_in[0];
    const float* coords = (const float*)d_in[1];
    float*       out    = (float*)d_out;
    const int n = in_sizes[0];

    const int pts_per_cta = TPB * PTS_PER_THREAD;             // 512
    const int blocks = (n + pts_per_cta - 1) / pts_per_cta;   // 64 for n=32768

    zero_out_kernel<<<1, 1>>>(out);
    contrastive_last_anchor_kernel<<<blocks, TPB>>>(labels, coords, out, n);
}